// round 8
// baseline (speedup 1.0000x reference)
#include <cuda_runtime.h>
#include <math.h>

#define N_TOK 8192
#define DIM   4096
#define NEXP  16
#define TPB   256
#define NWARP 8
#define TOK   32
#define KSL   (DIM / NWARP)       /* 512 k per warp */
#define KT    32                  /* k per tile */
#define NT    (KSL / KT)          /* 16 tiles */
#define XSTR  33                  /* x smem row stride (words) — conflict-free */

#define W_XS  (KT * XSTR)         /* 1056 f per warp */
#define SM_FLOATS (NWARP * W_XS + NWARP * TOK * NEXP + TOK * NEXP)
#define SM_BYTES  (SM_FLOATS * 4) /* 52352 B -> 2 CTAs/SM */

#define FMA2(acc, a, b) \
    asm("fma.rn.f32x2 %0, %1, %2, %0;" : "+l"(acc) : "l"(a), "l"(b))

__global__ void __launch_bounds__(TPB, 2)
router_kernel(const float* __restrict__ x, const float* __restrict__ gate,
              float* __restrict__ out, int out_size)
{
    extern __shared__ float sm[];
    float* part = sm + NWARP * W_XS;           // [NWARP][TOK][16]
    float* lg   = part + NWARP * TOK * NEXP;   // [TOK][16]

    const int tid = threadIdx.x;
    const int w = tid >> 5, l = tid & 31;
    const int tokBase = blockIdx.x * TOK;
    const int kw = w * KSL;

    float* xs = sm + w * W_XS;    // [KT][XSTR]  x transposed, stride 33

    // staging roles
    const int tokr = l >> 3;      // 0..3
    const int kq8  = l & 7;       // 0..7 (k quad within tile)
    // compute roles: lane = kq*8 + tg*2 + eg
    const int kq = l >> 3;        // 0..3 k-interleave
    const int tg = (l >> 1) & 3;  // token octet: tokens 8tg..8tg+7
    const int eg = l & 1;         // expert half: experts 8eg..8eg+7

    // gate base for this lane: row (kw+kq), experts 8eg..8eg+7 (two 16B chunks)
    // warp-wide per batch: 4 rows x 64B = 2 lines -> ~2 wavefronts per LDG.128
    const ulonglong2* gp =
        (const ulonglong2*)(gate + (size_t)(kw + kq) * NEXP + 8 * eg);

    // acc[i*4+ep]: token 8tg+i, expert pair {8eg+2ep, 8eg+2ep+1}
    unsigned long long acc[32];
#pragma unroll
    for (int i = 0; i < 32; i++) acc[i] = 0ull;

    // x prefetch: 8 rounds, (token 4rd+tokr, k quad kq8) — nL=4, full lines
    float4 xr[8];
#pragma unroll
    for (int rd = 0; rd < 8; rd++)
        xr[rd] = *(const float4*)(x + (size_t)(tokBase + 4 * rd + tokr) * DIM
                                  + kw + 4 * kq8);

#pragma unroll 1
    for (int t = 0; t < NT; t++) {
        __syncwarp();   // previous tile's smem reads complete

        // ---- STS x tile (STS.32, conflict-free: banks = 4kq8+j+4rd+tokr) ----
#pragma unroll
        for (int rd = 0; rd < 8; rd++) {
            float* col = xs + (4 * rd + tokr);
            col[(4 * kq8 + 0) * XSTR] = xr[rd].x;
            col[(4 * kq8 + 1) * XSTR] = xr[rd].y;
            col[(4 * kq8 + 2) * XSTR] = xr[rd].z;
            col[(4 * kq8 + 3) * XSTR] = xr[rd].w;
        }
        __syncwarp();

        // ---- prefetch x tile t+1 (lands during compute) ----
        if (t + 1 < NT) {
#pragma unroll
            for (int rd = 0; rd < 8; rd++)
                xr[rd] = *(const float4*)(x + (size_t)(tokBase + 4 * rd + tokr) * DIM
                                          + kw + (t + 1) * KT + 4 * kq8);
        }

        // ---- compute: 8 batches, lane's k = 4b + kq; gate direct from LDG ----
        // per-batch gate element offset (ulonglong2 units): row stride = 4
        const ulonglong2* gpt = gp + (size_t)t * KT * 4;
#pragma unroll
        for (int b = 0; b < 8; b++) {
            ulonglong2 Ga = gpt[(4 * b) * 4];        // experts 8eg+0..3 (16B)
            ulonglong2 Gb = gpt[(4 * b) * 4 + 1];    // experts 8eg+4..7 (16B)
            const float* xrow = xs + (4 * b + kq) * XSTR + 8 * tg;
#pragma unroll
            for (int i = 0; i < 8; i++) {
                float xv = xrow[i];                 // LDS.32, conflict-free
                unsigned long long xd;
                asm("mov.b64 %0, {%1,%1};" : "=l"(xd) : "f"(xv));
                FMA2(acc[i * 4 + 0], xd, Ga.x);
                FMA2(acc[i * 4 + 1], xd, Ga.y);
                FMA2(acc[i * 4 + 2], xd, Gb.x);
                FMA2(acc[i * 4 + 3], xd, Gb.y);
            }
        }
    }

    // ---- butterfly-reduce the 4-way k-interleave (lanes xor 8, 16) ----
#pragma unroll
    for (int i = 0; i < 32; i++) {
        float2 v = *(float2*)&acc[i];
        v.x += __shfl_xor_sync(0xffffffffu, v.x, 8);
        v.y += __shfl_xor_sync(0xffffffffu, v.y, 8);
        v.x += __shfl_xor_sync(0xffffffffu, v.x, 16);
        v.y += __shfl_xor_sync(0xffffffffu, v.y, 16);
        *(float2*)&acc[i] = v;
    }
    // lanes kq==0 hold the warp partial for (tg, eg)
    if (kq == 0) {
#pragma unroll
        for (int i = 0; i < 8; i++) {
            float* dst = part + (size_t)(w * TOK + 8 * tg + i) * NEXP + 8 * eg;
#pragma unroll
            for (int ep = 0; ep < 4; ep++)
                *(float2*)(dst + 2 * ep) = *(float2*)&acc[i * 4 + ep];
        }
    }
    __syncthreads();

    // ---- deterministic 8-warp tree reduce: thread -> (token, expert pair) ----
    {
        int tok = tid >> 3, e2 = (tid & 7) * 2;
        float2 s = make_float2(0.f, 0.f);
#pragma unroll
        for (int ww = 0; ww < NWARP; ww++) {
            float2 v = *(const float2*)(part + (size_t)(ww * TOK + tok) * NEXP + e2);
            s.x += v.x; s.y += v.y;
        }
        *(float2*)(lg + tok * NEXP + e2) = s;
    }
    __syncthreads();

    // ---- top-2 + sigmoid + transposed score writes ----
    if (tid < TOK) {
        int t = tid;
        float v[NEXP];
#pragma unroll
        for (int e = 0; e < NEXP; e++) v[e] = lg[t * NEXP + e];
        float v1 = -INFINITY, v2 = -INFINITY;
        int   i1 = -1,        i2 = -1;
#pragma unroll
        for (int e = 0; e < NEXP; e++) {
            float tv = v[e];
            if (tv > v1)      { v2 = v1; i2 = i1; v1 = tv; i1 = e; }
            else if (tv > v2) { v2 = tv; i2 = e; }
        }
        int gtok = tokBase + t;
#pragma unroll
        for (int e = 0; e < NEXP; e++) {
            float sc = (e == i1 || e == i2) ? (1.0f / (1.0f + expf(-v[e]))) : 0.0f;
            out[(size_t)e * N_TOK + gtok] = sc;   // 32 consecutive tokens: coalesced
        }
    }

    // ---- token_indices (second output region), values as floats ----
    if (out_size >= 2 * NEXP * N_TOK) {
        int e  = tid >> 4;            // 0..15
        int c2 = (tid & 15) * 2;      // token pair within block
        int gtok = tokBase + c2;
        float2 fv = make_float2((float)gtok, (float)(gtok + 1));
        *(float2*)(out + (size_t)NEXP * N_TOK + (size_t)e * N_TOK + gtok) = fv;
    }
}

extern "C" void kernel_launch(void* const* d_in, const int* in_sizes, int n_in,
                              void* d_out, int out_size)
{
    const float* x    = (const float*)d_in[0];
    const float* gate = (const float*)d_in[1];
    float* out = (float*)d_out;

    cudaFuncSetAttribute(router_kernel,
                         cudaFuncAttributeMaxDynamicSharedMemorySize, SM_BYTES);

    dim3 grid(N_TOK / TOK);   // 256 blocks, 2 CTAs/SM
    dim3 block(TPB);
    router_kernel<<<grid, block, SM_BYTES>>>(x, gate, out, out_size);
}